// round 5
// baseline (speedup 1.0000x reference)
#include <cuda_runtime.h>
#include <cstdint>

// Problem dims
#define Bq 256
#define Tq 512
#define Eq 512
#define Hq 1024
#define Cq 128
#define G4 4096   // 4*H
#define HC 1152   // H + C

// ---------------------------------------------------------------------------
// Device scratch (static globals; no runtime allocation allowed)
// ---------------------------------------------------------------------------
__device__ float g_gx0[(size_t)256 * Bq * G4];
__device__ float g_gx1[(size_t)256 * Bq * G4];
__device__ float g_A3[(size_t)Bq * Tq * HC];
__device__ float g_h[2][Bq * Hq];
__device__ float g_c[Bq * Hq];
__device__ float g_Wih[(size_t)G4 * Eq];
__device__ float g_Whh[(size_t)G4 * Hq];
__device__ float g_bias[G4];

__device__ __forceinline__ float* gxp(int t) {
    return (t < 256) ? (g_gx0 + (size_t)t * (Bq * G4))
                     : (g_gx1 + (size_t)(t - 256) * (Bq * G4));
}

// ---------------------------------------------------------------------------
// tf32 mma.sync m16n8k8 core + 3xTF32 split helpers
// ---------------------------------------------------------------------------
__device__ __forceinline__ void mma_tf32(float* d, const uint32_t* a, const uint32_t* b) {
    asm volatile(
        "mma.sync.aligned.m16n8k8.row.col.f32.tf32.tf32.f32 "
        "{%0,%1,%2,%3}, {%4,%5,%6,%7}, {%8,%9}, {%0,%1,%2,%3};\n"
        : "+f"(d[0]), "+f"(d[1]), "+f"(d[2]), "+f"(d[3])
        : "r"(a[0]), "r"(a[1]), "r"(a[2]), "r"(a[3]), "r"(b[0]), "r"(b[1]));
}

__device__ __forceinline__ uint32_t f2tf(float x) {
    uint32_t r;
    asm("cvt.rna.tf32.f32 %0, %1;\n" : "=r"(r) : "f"(x));
    return r;
}
// hi = tf32-rounded value, lo = tf32(residual)
__device__ __forceinline__ void tf_split(float v, uint32_t& hi, uint32_t& lo) {
    hi = f2tf(v);
    lo = f2tf(v - __uint_as_float(hi));
}

#define SROW 36            // 32 + 4 pad (floats) per smem row
#define ABUF 4608          // 128 * SROW floats per stage
#define SMEM_BYTES 73728   // (2*ABUF)*2 buffers * 4 bytes

// Tiled GEMM mainloop: C[128x128] += A[128xK] * B[128xK]^T (both K-major).
// BM=BN=128, BK=32, 256 threads (8 warps as 2x4 of 64x32 warp tiles),
// cp.async double-buffered. 3xTF32 compensated accumulation (~fp32 accuracy).
__device__ __forceinline__ void gemm_mainloop(
    const float* __restrict__ Ag, int lda,
    const float* __restrict__ Bg, int ldb,
    int kIters, float acc[4][4][4], float* sA, float* sB)
{
    const int tid  = threadIdx.x;
    const int lane = tid & 31, warp = tid >> 5;
    const int wm = warp >> 2, wn = warp & 3;
    const int g = lane >> 2, tg = lane & 3;
    const int lrow = tid >> 3;            // 0..31
    const int lc4  = (tid & 7) * 4;       // float offset of 16B chunk

    auto load_stage = [&](int buf, int k0) {
        #pragma unroll
        for (int i = 0; i < 4; ++i) {
            int row = lrow + i * 32;
            const float* ga = Ag + (size_t)row * lda + k0 + lc4;
            const float* gb = Bg + (size_t)row * ldb + k0 + lc4;
            uint32_t sa = (uint32_t)__cvta_generic_to_shared(sA + buf * ABUF + row * SROW + lc4);
            uint32_t sb = (uint32_t)__cvta_generic_to_shared(sB + buf * ABUF + row * SROW + lc4);
            asm volatile("cp.async.cg.shared.global [%0], [%1], 16;\n" :: "r"(sa), "l"(ga));
            asm volatile("cp.async.cg.shared.global [%0], [%1], 16;\n" :: "r"(sb), "l"(gb));
        }
    };

    load_stage(0, 0);
    asm volatile("cp.async.commit_group;\n");

    int buf = 0;
    for (int kt = 0; kt < kIters; ++kt) {
        if (kt + 1 < kIters) {
            load_stage(buf ^ 1, (kt + 1) * 32);
            asm volatile("cp.async.commit_group;\n");
            asm volatile("cp.async.wait_group 1;\n");
        } else {
            asm volatile("cp.async.wait_group 0;\n");
        }
        __syncthreads();

        const float* As = sA + buf * ABUF;
        const float* Bs = sB + buf * ABUF;
        #pragma unroll
        for (int kk = 0; kk < 4; ++kk) {
            const int k = kk * 8;
            uint32_t ah[4][4], al[4][4], bh[4][2], bl[4][2];
            #pragma unroll
            for (int mt = 0; mt < 4; ++mt) {
                int r = wm * 64 + mt * 16 + g;
                tf_split(As[r * SROW + k + tg],           ah[mt][0], al[mt][0]);
                tf_split(As[(r + 8) * SROW + k + tg],     ah[mt][1], al[mt][1]);
                tf_split(As[r * SROW + k + tg + 4],       ah[mt][2], al[mt][2]);
                tf_split(As[(r + 8) * SROW + k + tg + 4], ah[mt][3], al[mt][3]);
            }
            #pragma unroll
            for (int nt = 0; nt < 4; ++nt) {
                int cn = wn * 32 + nt * 8 + g;
                tf_split(Bs[cn * SROW + k + tg],     bh[nt][0], bl[nt][0]);
                tf_split(Bs[cn * SROW + k + tg + 4], bh[nt][1], bl[nt][1]);
            }
            // 3xTF32: acc += alo*bhi + ahi*blo + ahi*bhi (small terms first)
            #pragma unroll
            for (int mt = 0; mt < 4; ++mt)
                #pragma unroll
                for (int nt = 0; nt < 4; ++nt) {
                    mma_tf32(acc[mt][nt], al[mt], bh[nt]);
                    mma_tf32(acc[mt][nt], ah[mt], bl[nt]);
                    mma_tf32(acc[mt][nt], ah[mt], bh[nt]);
                }
        }
        __syncthreads();
        buf ^= 1;
    }
}

__device__ __forceinline__ void zero_acc(float acc[4][4][4]) {
    #pragma unroll
    for (int a = 0; a < 4; ++a)
        #pragma unroll
        for (int b = 0; b < 4; ++b)
            #pragma unroll
            for (int c = 0; c < 4; ++c)
                acc[a][b][c] = 0.f;
}

__device__ __forceinline__ float sigm(float x) { return 1.f / (1.f + __expf(-x)); }

// ---------------------------------------------------------------------------
// Prep: gate-interleave weights, sum biases
// ---------------------------------------------------------------------------
__global__ void k_prep(const float* __restrict__ Wih, const float* __restrict__ Whh,
                       const float* __restrict__ bih, const float* __restrict__ bhh)
{
    const int stride = gridDim.x * blockDim.x;
    const int tid0   = blockIdx.x * blockDim.x + threadIdx.x;
    for (size_t i = tid0; i < (size_t)G4 * Eq; i += stride) {
        int r = (int)(i / Eq), e = (int)(i % Eq);
        int gg = r >> 10, idx = r & 1023;
        g_Wih[((size_t)(idx * 4 + gg)) * Eq + e] = Wih[i];
    }
    for (size_t i = tid0; i < (size_t)G4 * Hq; i += stride) {
        int r = (int)(i / Hq), e = (int)(i % Hq);
        int gg = r >> 10, idx = r & 1023;
        g_Whh[((size_t)(idx * 4 + gg)) * Hq + e] = Whh[i];
    }
    for (int i = tid0; i < G4; i += stride) {
        int gg = i >> 10, idx = i & 1023;
        g_bias[idx * 4 + gg] = bih[i] + bhh[i];
    }
}

__global__ void k_zero() {
    const int n = Bq * Hq;
    for (int i = blockIdx.x * blockDim.x + threadIdx.x; i < n; i += gridDim.x * blockDim.x) {
        g_h[0][i] = 0.f;
        g_c[i]    = 0.f;
    }
}

// ---------------------------------------------------------------------------
// cate EMA scan -> A3 columns [1024, 1152)
// ---------------------------------------------------------------------------
__global__ void k_cate(const float* __restrict__ cate) {
    int idx = blockIdx.x * blockDim.x + threadIdx.x;   // B*C = 32768 threads
    int b = idx >> 7, cc = idx & 127;
    float p = 0.f;
    for (int t = 0; t < Tq; ++t) {
        float cv = cate[((size_t)b * Tq + t) * Cq + cc];
        p = (t == 0) ? cv : 0.9f * p + 0.1f * cv;
        g_A3[((size_t)b * Tq + t) * HC + Hq + cc] = p;
    }
}

// ---------------------------------------------------------------------------
// Phase 1: gatesX = x @ Wih_p^T + bias   (M=131072, N=4096, K=512)
// ---------------------------------------------------------------------------
__global__ void __launch_bounds__(256) k_gemm1(const float* __restrict__ x) {
    extern __shared__ float smem[];
    float* sA = smem;
    float* sB = smem + 2 * ABUF;
    const int m0 = blockIdx.y * 128;
    const int n0 = blockIdx.x * 128;

    float acc[4][4][4];
    zero_acc(acc);
    gemm_mainloop(x + (size_t)m0 * Eq, Eq, g_Wih + (size_t)n0 * Eq, Eq, Eq / 32, acc, sA, sB);

    const int lane = threadIdx.x & 31, warp = threadIdx.x >> 5;
    const int wm = warp >> 2, wn = warp & 3, g = lane >> 2, tg = lane & 3;
    #pragma unroll
    for (int mt = 0; mt < 4; ++mt) {
        #pragma unroll
        for (int half = 0; half < 2; ++half) {
            int rr = m0 + wm * 64 + mt * 16 + g + half * 8;
            int b = rr >> 9, tt = rr & 511;
            float* dst = gxp(tt) + (size_t)b * G4;
            #pragma unroll
            for (int nt = 0; nt < 4; ++nt) {
                int c = n0 + wn * 32 + nt * 8 + 2 * tg;
                float2 bias2 = *(const float2*)&g_bias[c];
                float2 v;
                v.x = acc[mt][nt][half * 2 + 0] + bias2.x;
                v.y = acc[mt][nt][half * 2 + 1] + bias2.y;
                *(float2*)&dst[c] = v;
            }
        }
    }
}

// ---------------------------------------------------------------------------
// Phase 2: one timestep. gates = h_prev @ Whh_p^T + gatesX[t]; fused LSTM cell.
// Grid (32, 2): N-tiles x M-tiles. Gate quads live in 4 adjacent columns.
// ---------------------------------------------------------------------------
__global__ void __launch_bounds__(256) k_step(int t, int p) {
    extern __shared__ float smem[];
    float* sA = smem;
    float* sB = smem + 2 * ABUF;
    const int m0 = blockIdx.y * 128;
    const int n0 = blockIdx.x * 128;

    float acc[4][4][4];
    zero_acc(acc);
    gemm_mainloop(g_h[p] + (size_t)m0 * Hq, Hq, g_Whh + (size_t)n0 * Hq, Hq, Hq / 32, acc, sA, sB);

    // Dump accumulators into smem (reuse AB buffers: 128*132*4 = 67584 <= 73728)
    float* Cs = smem;
    {
        const int lane = threadIdx.x & 31, warp = threadIdx.x >> 5;
        const int wm = warp >> 2, wn = warp & 3, g = lane >> 2, tg = lane & 3;
        #pragma unroll
        for (int mt = 0; mt < 4; ++mt)
            #pragma unroll
            for (int half = 0; half < 2; ++half) {
                int r = wm * 64 + mt * 16 + g + half * 8;
                #pragma unroll
                for (int nt = 0; nt < 4; ++nt) {
                    int c = wn * 32 + nt * 8 + 2 * tg;
                    float2 v;
                    v.x = acc[mt][nt][half * 2 + 0];
                    v.y = acc[mt][nt][half * 2 + 1];
                    *(float2*)&Cs[r * 132 + c] = v;
                }
            }
    }
    __syncthreads();

    // Fused LSTM elementwise: tile covers 128 batch rows x 32 h-indices.
    const int hbase = n0 >> 2;
    const int pn = p ^ 1;
    for (int it = threadIdx.x; it < 128 * 32; it += 256) {
        int r = it >> 5, j = it & 31;
        int b = m0 + r;
        float4 gv = *(const float4*)&Cs[r * 132 + 4 * j];
        const float* gxrow = gxp(t) + (size_t)b * G4 + n0;
        float4 xv = *(const float4*)&gxrow[4 * j];
        float i_ = sigm(gv.x + xv.x);
        float f_ = sigm(gv.y + xv.y);
        float gg = tanhf(gv.z + xv.z);
        float o_ = sigm(gv.w + xv.w);
        int hidx = hbase + j;
        size_t ci = (size_t)b * Hq + hidx;
        float c_new = f_ * g_c[ci] + i_ * gg;
        g_c[ci] = c_new;
        float h_new = o_ * tanhf(c_new);
        g_h[pn][ci] = h_new;
        g_A3[((size_t)b * Tq + t) * HC + hidx] = h_new;
    }
}

// ---------------------------------------------------------------------------
// Phase 3: out = A3 @ W_lin^T + b_lin, with seq-length mask (inactive -> b_lin)
// (M=131072, N=512, K=1152)
// ---------------------------------------------------------------------------
__global__ void __launch_bounds__(256) k_gemm2(const float* __restrict__ Wlin,
                                               const float* __restrict__ blin,
                                               const int* __restrict__ seq,
                                               float* __restrict__ out)
{
    extern __shared__ float smem[];
    float* sA = smem;
    float* sB = smem + 2 * ABUF;
    const int m0 = blockIdx.y * 128;
    const int n0 = blockIdx.x * 128;

    float acc[4][4][4];
    zero_acc(acc);
    gemm_mainloop(g_A3 + (size_t)m0 * HC, HC, Wlin + (size_t)n0 * HC, HC, HC / 32, acc, sA, sB);

    const int lane = threadIdx.x & 31, warp = threadIdx.x >> 5;
    const int wm = warp >> 2, wn = warp & 3, g = lane >> 2, tg = lane & 3;
    #pragma unroll
    for (int mt = 0; mt < 4; ++mt) {
        #pragma unroll
        for (int half = 0; half < 2; ++half) {
            int rr = m0 + wm * 64 + mt * 16 + g + half * 8;
            int b = rr >> 9, tt = rr & 511;
            bool active = tt < seq[b];
            float* dst = out + (size_t)rr * Eq;
            #pragma unroll
            for (int nt = 0; nt < 4; ++nt) {
                int c = n0 + wn * 32 + nt * 8 + 2 * tg;
                float2 bl = *(const float2*)&blin[c];
                float2 v;
                v.x = active ? acc[mt][nt][half * 2 + 0] + bl.x : bl.x;
                v.y = active ? acc[mt][nt][half * 2 + 1] + bl.y : bl.y;
                *(float2*)&dst[c] = v;
            }
        }
    }
}

// ---------------------------------------------------------------------------
// Launch
// ---------------------------------------------------------------------------
extern "C" void kernel_launch(void* const* d_in, const int* in_sizes, int n_in,
                              void* d_out, int out_size)
{
    (void)in_sizes; (void)n_in; (void)out_size;
    const float* x    = (const float*)d_in[0];
    const float* cate = (const float*)d_in[1];
    const int*   seq  = (const int*)d_in[2];
    const float* Wih  = (const float*)d_in[3];
    const float* Whh  = (const float*)d_in[4];
    const float* bih  = (const float*)d_in[5];
    const float* bhh  = (const float*)d_in[6];
    const float* Wlin = (const float*)d_in[7];
    const float* blin = (const float*)d_in[8];
    float* out = (float*)d_out;

    cudaFuncSetAttribute(k_gemm1, cudaFuncAttributeMaxDynamicSharedMemorySize, SMEM_BYTES);
    cudaFuncSetAttribute(k_step,  cudaFuncAttributeMaxDynamicSharedMemorySize, SMEM_BYTES);
    cudaFuncSetAttribute(k_gemm2, cudaFuncAttributeMaxDynamicSharedMemorySize, SMEM_BYTES);

    k_zero<<<512, 256>>>();
    k_prep<<<2048, 256>>>(Wih, Whh, bih, bhh);
    k_cate<<<128, 256>>>(cate);

    {
        dim3 grid(32, 1024);   // N-tiles x M-tiles
        k_gemm1<<<grid, 256, SMEM_BYTES>>>(x);
    }
    for (int t = 0; t < Tq; ++t) {
        dim3 grid(32, 2);
        k_step<<<grid, 256, SMEM_BYTES>>>(t, t & 1);
    }
    {
        dim3 grid(4, 1024);
        k_gemm2<<<grid, 256, SMEM_BYTES>>>(Wlin, blin, seq, out);
    }
}

// round 9
// speedup vs baseline: 2.0387x; 2.0387x over previous
#include <cuda_runtime.h>
#include <cuda_bf16.h>
#include <cstdint>

// Problem dims
#define Bq 256
#define Tq 512
#define Eq 512
#define Hq 1024
#define Cq 128
#define G4 4096   // 4*H
#define HC 1152   // H + C

// ---------------------------------------------------------------------------
// Device scratch (static globals; no runtime allocation allowed)
// ---------------------------------------------------------------------------
__device__ float g_gx0[(size_t)256 * Bq * G4];
__device__ float g_gx1[(size_t)256 * Bq * G4];
__device__ float g_A3[(size_t)Bq * Tq * HC];
// h state as bf16 hi/lo pairs (ping-pong)
__device__ __nv_bfloat16 g_hh[2][Bq * Hq];
__device__ __nv_bfloat16 g_hl[2][Bq * Hq];
__device__ float g_c[Bq * Hq];
// Gate-interleaved weights: row nr = idx*4 + gate
__device__ float g_Wih[(size_t)G4 * Eq];
__device__ __nv_bfloat16 g_Whh_h[(size_t)G4 * Hq];
__device__ __nv_bfloat16 g_Whh_l[(size_t)G4 * Hq];
__device__ float g_bias[G4];

__device__ __forceinline__ float* gxp(int t) {
    return (t < 256) ? (g_gx0 + (size_t)t * (Bq * G4))
                     : (g_gx1 + (size_t)(t - 256) * (Bq * G4));
}

// ---------------------------------------------------------------------------
// MMA cores
// ---------------------------------------------------------------------------
__device__ __forceinline__ void mma_tf32(float* d, const uint32_t* a, const uint32_t* b) {
    asm volatile(
        "mma.sync.aligned.m16n8k8.row.col.f32.tf32.tf32.f32 "
        "{%0,%1,%2,%3}, {%4,%5,%6,%7}, {%8,%9}, {%0,%1,%2,%3};\n"
        : "+f"(d[0]), "+f"(d[1]), "+f"(d[2]), "+f"(d[3])
        : "r"(a[0]), "r"(a[1]), "r"(a[2]), "r"(a[3]), "r"(b[0]), "r"(b[1]));
}

__device__ __forceinline__ void mma_bf16(float* d, const uint32_t* a, const uint32_t* b) {
    asm volatile(
        "mma.sync.aligned.m16n8k16.row.col.f32.bf16.bf16.f32 "
        "{%0,%1,%2,%3}, {%4,%5,%6,%7}, {%8,%9}, {%0,%1,%2,%3};\n"
        : "+f"(d[0]), "+f"(d[1]), "+f"(d[2]), "+f"(d[3])
        : "r"(a[0]), "r"(a[1]), "r"(a[2]), "r"(a[3]), "r"(b[0]), "r"(b[1]));
}

__device__ __forceinline__ uint32_t f2tf(float x) {
    uint32_t r;
    asm("cvt.rna.tf32.f32 %0, %1;\n" : "=r"(r) : "f"(x));
    return r;
}
__device__ __forceinline__ void tf_split(float v, uint32_t& hi, uint32_t& lo) {
    hi = f2tf(v);
    lo = f2tf(v - __uint_as_float(hi));
}

#define SROW 36            // fp32 path: 32 + 4 pad floats per smem row
#define ABUF 4608          // 128 * SROW floats per stage
#define SMEM_BYTES 73728

// ---------------------------------------------------------------------------
// fp32 (3xTF32) tiled mainloop: C[128x128] += A[128xK] * B[128xK]^T
// ---------------------------------------------------------------------------
__device__ __forceinline__ void gemm_mainloop(
    const float* __restrict__ Ag, int lda,
    const float* __restrict__ Bg, int ldb,
    int kIters, float acc[4][4][4], float* sA, float* sB)
{
    const int tid  = threadIdx.x;
    const int lane = tid & 31, warp = tid >> 5;
    const int wm = warp >> 2, wn = warp & 3;
    const int g = lane >> 2, tg = lane & 3;
    const int lrow = tid >> 3;
    const int lc4  = (tid & 7) * 4;

    auto load_stage = [&](int buf, int k0) {
        #pragma unroll
        for (int i = 0; i < 4; ++i) {
            int row = lrow + i * 32;
            const float* ga = Ag + (size_t)row * lda + k0 + lc4;
            const float* gb = Bg + (size_t)row * ldb + k0 + lc4;
            uint32_t sa = (uint32_t)__cvta_generic_to_shared(sA + buf * ABUF + row * SROW + lc4);
            uint32_t sb = (uint32_t)__cvta_generic_to_shared(sB + buf * ABUF + row * SROW + lc4);
            asm volatile("cp.async.cg.shared.global [%0], [%1], 16;\n" :: "r"(sa), "l"(ga));
            asm volatile("cp.async.cg.shared.global [%0], [%1], 16;\n" :: "r"(sb), "l"(gb));
        }
    };

    load_stage(0, 0);
    asm volatile("cp.async.commit_group;\n");

    int buf = 0;
    for (int kt = 0; kt < kIters; ++kt) {
        if (kt + 1 < kIters) {
            load_stage(buf ^ 1, (kt + 1) * 32);
            asm volatile("cp.async.commit_group;\n");
            asm volatile("cp.async.wait_group 1;\n");
        } else {
            asm volatile("cp.async.wait_group 0;\n");
        }
        __syncthreads();

        const float* As = sA + buf * ABUF;
        const float* Bs = sB + buf * ABUF;
        #pragma unroll
        for (int kk = 0; kk < 4; ++kk) {
            const int k = kk * 8;
            uint32_t ah[4][4], al[4][4], bh[4][2], bl[4][2];
            #pragma unroll
            for (int mt = 0; mt < 4; ++mt) {
                int r = wm * 64 + mt * 16 + g;
                tf_split(As[r * SROW + k + tg],           ah[mt][0], al[mt][0]);
                tf_split(As[(r + 8) * SROW + k + tg],     ah[mt][1], al[mt][1]);
                tf_split(As[r * SROW + k + tg + 4],       ah[mt][2], al[mt][2]);
                tf_split(As[(r + 8) * SROW + k + tg + 4], ah[mt][3], al[mt][3]);
            }
            #pragma unroll
            for (int nt = 0; nt < 4; ++nt) {
                int cn = wn * 32 + nt * 8 + g;
                tf_split(Bs[cn * SROW + k + tg],     bh[nt][0], bl[nt][0]);
                tf_split(Bs[cn * SROW + k + tg + 4], bh[nt][1], bl[nt][1]);
            }
            #pragma unroll
            for (int mt = 0; mt < 4; ++mt)
                #pragma unroll
                for (int nt = 0; nt < 4; ++nt) {
                    mma_tf32(acc[mt][nt], al[mt], bh[nt]);
                    mma_tf32(acc[mt][nt], ah[mt], bl[nt]);
                    mma_tf32(acc[mt][nt], ah[mt], bh[nt]);
                }
        }
        __syncthreads();
        buf ^= 1;
    }
}

__device__ __forceinline__ void zero_acc4(float acc[4][4][4]) {
    #pragma unroll
    for (int a = 0; a < 4; ++a)
        #pragma unroll
        for (int b = 0; b < 4; ++b)
            #pragma unroll
            for (int c = 0; c < 4; ++c)
                acc[a][b][c] = 0.f;
}

__device__ __forceinline__ float sigm(float x) { return 1.f / (1.f + __expf(-x)); }

// ---------------------------------------------------------------------------
// Prep: gate-interleave weights (Wih fp32, Whh bf16 hi/lo), sum biases
// ---------------------------------------------------------------------------
__global__ void k_prep(const float* __restrict__ Wih, const float* __restrict__ Whh,
                       const float* __restrict__ bih, const float* __restrict__ bhh)
{
    const int stride = gridDim.x * blockDim.x;
    const int tid0   = blockIdx.x * blockDim.x + threadIdx.x;
    for (size_t i = tid0; i < (size_t)G4 * Eq; i += stride) {
        int r = (int)(i / Eq), e = (int)(i % Eq);
        int gg = r >> 10, idx = r & 1023;
        g_Wih[((size_t)(idx * 4 + gg)) * Eq + e] = Wih[i];
    }
    for (size_t i = tid0; i < (size_t)G4 * Hq; i += stride) {
        int r = (int)(i / Hq), e = (int)(i % Hq);
        int gg = r >> 10, idx = r & 1023;
        float v = Whh[i];
        __nv_bfloat16 hi = __float2bfloat16(v);
        __nv_bfloat16 lo = __float2bfloat16(v - __bfloat162float(hi));
        size_t o = ((size_t)(idx * 4 + gg)) * Hq + e;
        g_Whh_h[o] = hi;
        g_Whh_l[o] = lo;
    }
    for (int i = tid0; i < G4; i += stride) {
        int gg = i >> 10, idx = i & 1023;
        g_bias[idx * 4 + gg] = bih[i] + bhh[i];
    }
}

__global__ void k_zero() {
    const int n = Bq * Hq;
    const __nv_bfloat16 z = __float2bfloat16(0.f);
    for (int i = blockIdx.x * blockDim.x + threadIdx.x; i < n; i += gridDim.x * blockDim.x) {
        g_hh[0][i] = z;
        g_hl[0][i] = z;
        g_c[i]     = 0.f;
    }
}

// ---------------------------------------------------------------------------
// cate EMA scan -> A3 columns [1024, 1152)
// ---------------------------------------------------------------------------
__global__ void k_cate(const float* __restrict__ cate) {
    int idx = blockIdx.x * blockDim.x + threadIdx.x;
    int b = idx >> 7, cc = idx & 127;
    float p = 0.f;
    for (int t = 0; t < Tq; ++t) {
        float cv = cate[((size_t)b * Tq + t) * Cq + cc];
        p = (t == 0) ? cv : 0.9f * p + 0.1f * cv;
        g_A3[((size_t)b * Tq + t) * HC + Hq + cc] = p;
    }
}

// ---------------------------------------------------------------------------
// Phase 1: gatesX = x @ Wih_p^T + bias   (M=131072, N=4096, K=512)
// ---------------------------------------------------------------------------
__global__ void __launch_bounds__(256) k_gemm1(const float* __restrict__ x) {
    extern __shared__ float smem[];
    float* sA = smem;
    float* sB = smem + 2 * ABUF;
    const int m0 = blockIdx.y * 128;
    const int n0 = blockIdx.x * 128;

    float acc[4][4][4];
    zero_acc4(acc);
    gemm_mainloop(x + (size_t)m0 * Eq, Eq, g_Wih + (size_t)n0 * Eq, Eq, Eq / 32, acc, sA, sB);

    const int lane = threadIdx.x & 31, warp = threadIdx.x >> 5;
    const int wm = warp >> 2, wn = warp & 3, g = lane >> 2, tg = lane & 3;
    #pragma unroll
    for (int mt = 0; mt < 4; ++mt) {
        #pragma unroll
        for (int half = 0; half < 2; ++half) {
            int rr = m0 + wm * 64 + mt * 16 + g + half * 8;
            int b = rr >> 9, tt = rr & 511;
            float* dst = gxp(tt) + (size_t)b * G4;
            #pragma unroll
            for (int nt = 0; nt < 4; ++nt) {
                int c = n0 + wn * 32 + nt * 8 + 2 * tg;
                float2 bias2 = *(const float2*)&g_bias[c];
                float2 v;
                v.x = acc[mt][nt][half * 2 + 0] + bias2.x;
                v.y = acc[mt][nt][half * 2 + 1] + bias2.y;
                *(float2*)&dst[c] = v;
            }
        }
    }
}

// ---------------------------------------------------------------------------
// Phase 2 (recurrence step): 3xBF16 compensated GEMM, BM=64 BN=128 BK=32.
// Grid (32, 4) = 128 CTAs. Fused LSTM cell epilogue.
// ---------------------------------------------------------------------------
#define SROWB 40                      // bf16 elems per smem row (32 + 8 pad)
#define ASTG  (64 * SROWB)            // one hi or lo A block (bf16 elems)
#define ASTAGE (2 * ASTG)
#define BSTG  (128 * SROWB)
#define BSTAGE (2 * BSTG)
#define STEP_SMEM ((2 * ASTAGE + 2 * BSTAGE) * 2)   // 61440 bytes

__global__ void __launch_bounds__(256) k_step(int t, int p) {
    extern __shared__ __nv_bfloat16 smem_b[];
    __nv_bfloat16* sA = smem_b;
    __nv_bfloat16* sB = smem_b + 2 * ASTAGE;

    const int m0 = blockIdx.y * 64;
    const int n0 = blockIdx.x * 128;

    const __nv_bfloat16* Ah = g_hh[p] + (size_t)m0 * Hq;
    const __nv_bfloat16* Al = g_hl[p] + (size_t)m0 * Hq;
    const __nv_bfloat16* Bh = g_Whh_h + (size_t)n0 * Hq;
    const __nv_bfloat16* Bl = g_Whh_l + (size_t)n0 * Hq;

    const int tid  = threadIdx.x;
    const int lane = tid & 31, warp = tid >> 5;
    const int wm = warp >> 2, wn = warp & 3;       // 2 x 4 warp grid, warp tile 32x32
    const int g = lane >> 2, tg = lane & 3;

    float acc[2][4][4];
    #pragma unroll
    for (int a = 0; a < 2; ++a)
        #pragma unroll
        for (int b = 0; b < 4; ++b)
            #pragma unroll
            for (int c = 0; c < 4; ++c)
                acc[a][b][c] = 0.f;

    auto load_stage = [&](int buf, int k0) {
        // A: 64 rows x 32 cols bf16, hi+lo. 4 chunks of 16B per row per matrix.
        {
            int row = tid >> 2, ch = tid & 3;
            const __nv_bfloat16* gh = Ah + (size_t)row * Hq + k0 + ch * 8;
            const __nv_bfloat16* gl = Al + (size_t)row * Hq + k0 + ch * 8;
            uint32_t dh = (uint32_t)__cvta_generic_to_shared(sA + buf * ASTAGE + row * SROWB + ch * 8);
            uint32_t dl = dh + ASTG * 2;  // bytes
            asm volatile("cp.async.cg.shared.global [%0], [%1], 16;\n" :: "r"(dh), "l"(gh));
            asm volatile("cp.async.cg.shared.global [%0], [%1], 16;\n" :: "r"(dl), "l"(gl));
        }
        // B: 128 rows x 32 cols bf16, hi+lo.
        #pragma unroll
        for (int i = 0; i < 2; ++i) {
            int slot = tid + 256 * i;
            int row = slot >> 2, ch = slot & 3;
            const __nv_bfloat16* gh = Bh + (size_t)row * Hq + k0 + ch * 8;
            const __nv_bfloat16* gl = Bl + (size_t)row * Hq + k0 + ch * 8;
            uint32_t dh = (uint32_t)__cvta_generic_to_shared(sB + buf * BSTAGE + row * SROWB + ch * 8);
            uint32_t dl = dh + BSTG * 2;
            asm volatile("cp.async.cg.shared.global [%0], [%1], 16;\n" :: "r"(dh), "l"(gh));
            asm volatile("cp.async.cg.shared.global [%0], [%1], 16;\n" :: "r"(dl), "l"(gl));
        }
    };

    const int kIters = Hq / 32;
    load_stage(0, 0);
    asm volatile("cp.async.commit_group;\n");

    int buf = 0;
    for (int kt = 0; kt < kIters; ++kt) {
        if (kt + 1 < kIters) {
            load_stage(buf ^ 1, (kt + 1) * 32);
            asm volatile("cp.async.commit_group;\n");
            asm volatile("cp.async.wait_group 1;\n");
        } else {
            asm volatile("cp.async.wait_group 0;\n");
        }
        __syncthreads();

        const __nv_bfloat16* As = sA + buf * ASTAGE;
        const __nv_bfloat16* Bs = sB + buf * BSTAGE;
        #pragma unroll
        for (int kk = 0; kk < 2; ++kk) {
            const int c0 = tg + 8 * kk;   // 32-bit word index within row
            uint32_t ah[2][4], al[2][4], bh[4][2], bl[4][2];
            #pragma unroll
            for (int mt = 0; mt < 2; ++mt) {
                int r = wm * 32 + mt * 16 + g;
                const uint32_t* ph  = (const uint32_t*)(As + r * SROWB);
                const uint32_t* ph8 = (const uint32_t*)(As + (r + 8) * SROWB);
                const uint32_t* pl  = (const uint32_t*)(As + ASTG + r * SROWB);
                const uint32_t* pl8 = (const uint32_t*)(As + ASTG + (r + 8) * SROWB);
                ah[mt][0] = ph[c0];  ah[mt][1] = ph8[c0];
                ah[mt][2] = ph[c0 + 4]; ah[mt][3] = ph8[c0 + 4];
                al[mt][0] = pl[c0];  al[mt][1] = pl8[c0];
                al[mt][2] = pl[c0 + 4]; al[mt][3] = pl8[c0 + 4];
            }
            #pragma unroll
            for (int nt = 0; nt < 4; ++nt) {
                int cn = wn * 32 + nt * 8 + g;
                const uint32_t* qh = (const uint32_t*)(Bs + cn * SROWB);
                const uint32_t* ql = (const uint32_t*)(Bs + BSTG + cn * SROWB);
                bh[nt][0] = qh[c0]; bh[nt][1] = qh[c0 + 4];
                bl[nt][0] = ql[c0]; bl[nt][1] = ql[c0 + 4];
            }
            #pragma unroll
            for (int mt = 0; mt < 2; ++mt)
                #pragma unroll
                for (int nt = 0; nt < 4; ++nt) {
                    mma_bf16(acc[mt][nt], al[mt], bh[nt]);
                    mma_bf16(acc[mt][nt], ah[mt], bl[nt]);
                    mma_bf16(acc[mt][nt], ah[mt], bh[nt]);
                }
        }
        __syncthreads();
        buf ^= 1;
    }

    // Dump accumulators into smem: 64 rows x 132 floats = 33792B <= 61440B
    float* Cs = (float*)smem_b;
    #pragma unroll
    for (int mt = 0; mt < 2; ++mt)
        #pragma unroll
        for (int half = 0; half < 2; ++half) {
            int r = wm * 32 + mt * 16 + g + half * 8;
            #pragma unroll
            for (int nt = 0; nt < 4; ++nt) {
                int c = wn * 32 + nt * 8 + 2 * tg;
                float2 v;
                v.x = acc[mt][nt][half * 2 + 0];
                v.y = acc[mt][nt][half * 2 + 1];
                *(float2*)&Cs[r * 132 + c] = v;
            }
        }
    __syncthreads();

    // Fused LSTM elementwise: tile covers 64 batch rows x 32 h-indices.
    const int hbase = n0 >> 2;
    const int pn = p ^ 1;
    for (int it = tid; it < 64 * 32; it += 256) {
        int r = it >> 5, j = it & 31;
        int b = m0 + r;
        float4 gv = *(const float4*)&Cs[r * 132 + 4 * j];
        const float* gxrow = gxp(t) + (size_t)b * G4 + n0;
        float4 xv = *(const float4*)&gxrow[4 * j];
        float i_ = sigm(gv.x + xv.x);
        float f_ = sigm(gv.y + xv.y);
        float gg = tanhf(gv.z + xv.z);
        float o_ = sigm(gv.w + xv.w);
        int hidx = hbase + j;
        size_t ci = (size_t)b * Hq + hidx;
        float c_new = f_ * g_c[ci] + i_ * gg;
        g_c[ci] = c_new;
        float h_new = o_ * tanhf(c_new);
        __nv_bfloat16 hi = __float2bfloat16(h_new);
        __nv_bfloat16 lo = __float2bfloat16(h_new - __bfloat162float(hi));
        g_hh[pn][ci] = hi;
        g_hl[pn][ci] = lo;
        g_A3[((size_t)b * Tq + t) * HC + hidx] = h_new;
    }
}

// ---------------------------------------------------------------------------
// Phase 3: out = A3 @ W_lin^T + b_lin, with seq-length mask
// ---------------------------------------------------------------------------
__global__ void __launch_bounds__(256) k_gemm2(const float* __restrict__ Wlin,
                                               const float* __restrict__ blin,
                                               const int* __restrict__ seq,
                                               float* __restrict__ out)
{
    extern __shared__ float smem[];
    float* sA = smem;
    float* sB = smem + 2 * ABUF;
    const int m0 = blockIdx.y * 128;
    const int n0 = blockIdx.x * 128;

    float acc[4][4][4];
    zero_acc4(acc);
    gemm_mainloop(g_A3 + (size_t)m0 * HC, HC, Wlin + (size_t)n0 * HC, HC, HC / 32, acc, sA, sB);

    const int lane = threadIdx.x & 31, warp = threadIdx.x >> 5;
    const int wm = warp >> 2, wn = warp & 3, g = lane >> 2, tg = lane & 3;
    #pragma unroll
    for (int mt = 0; mt < 4; ++mt) {
        #pragma unroll
        for (int half = 0; half < 2; ++half) {
            int rr = m0 + wm * 64 + mt * 16 + g + half * 8;
            int b = rr >> 9, tt = rr & 511;
            bool active = tt < seq[b];
            float* dst = out + (size_t)rr * Eq;
            #pragma unroll
            for (int nt = 0; nt < 4; ++nt) {
                int c = n0 + wn * 32 + nt * 8 + 2 * tg;
                float2 bl = *(const float2*)&blin[c];
                float2 v;
                v.x = active ? acc[mt][nt][half * 2 + 0] + bl.x : bl.x;
                v.y = active ? acc[mt][nt][half * 2 + 1] + bl.y : bl.y;
                *(float2*)&dst[c] = v;
            }
        }
    }
}

// ---------------------------------------------------------------------------
// Launch
// ---------------------------------------------------------------------------
extern "C" void kernel_launch(void* const* d_in, const int* in_sizes, int n_in,
                              void* d_out, int out_size)
{
    (void)in_sizes; (void)n_in; (void)out_size;
    const float* x    = (const float*)d_in[0];
    const float* cate = (const float*)d_in[1];
    const int*   seq  = (const int*)d_in[2];
    const float* Wih  = (const float*)d_in[3];
    const float* Whh  = (const float*)d_in[4];
    const float* bih  = (const float*)d_in[5];
    const float* bhh  = (const float*)d_in[6];
    const float* Wlin = (const float*)d_in[7];
    const float* blin = (const float*)d_in[8];
    float* out = (float*)d_out;

    cudaFuncSetAttribute(k_gemm1, cudaFuncAttributeMaxDynamicSharedMemorySize, SMEM_BYTES);
    cudaFuncSetAttribute(k_step,  cudaFuncAttributeMaxDynamicSharedMemorySize, STEP_SMEM);
    cudaFuncSetAttribute(k_gemm2, cudaFuncAttributeMaxDynamicSharedMemorySize, SMEM_BYTES);

    k_zero<<<512, 256>>>();
    k_prep<<<2048, 256>>>(Wih, Whh, bih, bhh);
    k_cate<<<128, 256>>>(cate);

    {
        dim3 grid(32, 1024);   // N-tiles x M-tiles
        k_gemm1<<<grid, 256, SMEM_BYTES>>>(x);
    }
    for (int t = 0; t < Tq; ++t) {
        dim3 grid(32, 4);      // N-tiles x M-tiles (BM=64) -> 128 CTAs
        k_step<<<grid, 256, STEP_SMEM>>>(t, t & 1);
    }
    {
        dim3 grid(4, 1024);
        k_gemm2<<<grid, 256, SMEM_BYTES>>>(Wlin, blin, seq, out);
    }
}